// round 13
// baseline (speedup 1.0000x reference)
#include <cuda_runtime.h>
#include <cstdint>

#define TS 4096
#define NH 16
#define HD 128
#define NP 512
#define BM 128
#define BN 64
#define NT 512            // 16 warps: pair (wq 0..7) x (wk 0..1)
#define SCALE 0.08838834764831845f

// ---- device scratch ----
__device__ uint32_t g_khi[3*16*512*64];
__device__ uint32_t g_klo[3*16*512*64];
__device__ uint32_t g_vtf[3*16*128*256];   // fp16 V^T packed pairs
__device__ uint32_t g_qhi[4096*16*64];
__device__ uint32_t g_qlo[4096*16*64];

static __device__ __forceinline__ uint32_t s2u(const void* p){
  uint32_t a; asm("{ .reg .u64 t; cvta.to.shared.u64 t, %1; cvt.u32.u64 %0, t; }" : "=r"(a) : "l"(p)); return a;
}
static __device__ __forceinline__ uint16_t f2bf(float x){
  uint16_t r; asm("cvt.rn.bf16.f32 %0, %1;" : "=h"(r) : "f"(x)); return r;
}
static __device__ __forceinline__ float bf2f(uint16_t b){
  return __uint_as_float(((uint32_t)b) << 16);
}
static __device__ __forceinline__ uint16_t f2h(float x){
  uint16_t r; asm("cvt.rn.f16.f32 %0, %1;" : "=h"(r) : "f"(x)); return r;
}
static __device__ __forceinline__ uint32_t packbf(float x0, float x1){
  uint32_t r; asm("cvt.rn.bf16x2.f32 %0, %1, %2;" : "=r"(r) : "f"(x1), "f"(x0)); return r;
}
static __device__ __forceinline__ uint32_t packh(float x0, float x1){
  uint32_t r; asm("cvt.rn.f16x2.f32 %0, %1, %2;" : "=r"(r) : "f"(x1), "f"(x0)); return r;
}
static __device__ __forceinline__ void splitpair(float x0, float x1, uint32_t& hi, uint32_t& lo){
  hi = packbf(x0, x1);
  float h0 = bf2f((uint16_t)(hi & 0xffffu));
  float h1 = bf2f((uint16_t)(hi >> 16));
  lo = packbf(x0 - h0, x1 - h1);
}
static __device__ __forceinline__ void mma_bf16(float* d, const uint32_t* a, const uint32_t* b){
  asm volatile(
    "mma.sync.aligned.m16n8k16.row.col.f32.bf16.bf16.f32 "
    "{%0,%1,%2,%3}, {%4,%5,%6,%7}, {%8,%9}, {%0,%1,%2,%3};"
    : "+f"(d[0]), "+f"(d[1]), "+f"(d[2]), "+f"(d[3])
    : "r"(a[0]), "r"(a[1]), "r"(a[2]), "r"(a[3]), "r"(b[0]), "r"(b[1]));
}
static __device__ __forceinline__ void mma_f16(float* d, const uint32_t* a, const uint32_t* b){
  asm volatile(
    "mma.sync.aligned.m16n8k16.row.col.f32.f16.f16.f32 "
    "{%0,%1,%2,%3}, {%4,%5,%6,%7}, {%8,%9}, {%0,%1,%2,%3};"
    : "+f"(d[0]), "+f"(d[1]), "+f"(d[2]), "+f"(d[3])
    : "r"(a[0]), "r"(a[1]), "r"(a[2]), "r"(a[3]), "r"(b[0]), "r"(b[1]));
}
static __device__ __forceinline__ void ldsm4(uint32_t& r0, uint32_t& r1, uint32_t& r2, uint32_t& r3, uint32_t addr){
  asm volatile("ldmatrix.sync.aligned.m8n8.x4.shared.b16 {%0,%1,%2,%3}, [%4];"
               : "=r"(r0), "=r"(r1), "=r"(r2), "=r"(r3) : "r"(addr));
}
static __device__ __forceinline__ void cpa16(uint32_t dst, const void* src){
  asm volatile("cp.async.cg.shared.global [%0], [%1], 16;" :: "r"(dst), "l"(src) : "memory");
}
#define CP_COMMIT() asm volatile("cp.async.commit_group;" ::: "memory")
#define CP_WAIT0()  asm volatile("cp.async.wait_group 0;" ::: "memory")

// ================= pre-pass kernels (verified) =================
__global__ void prep_k(const float* __restrict__ k, const float* __restrict__ rk){
  int g = blockIdx.x * blockDim.x + threadIdx.x;
  int dp = g & 63; int r = g >> 6;
  int j = r & 511; r >>= 9;
  int h = r & 15;  int blk = r >> 4;
  const float* src = (blk == 0)
    ? (k  + ((size_t)j*NH + h)*HD + dp*2)
    : (rk + (((size_t)(blk-1)*NP + j)*NH + h)*HD + dp*2);
  float2 x = *(const float2*)src;
  uint32_t hi, lo; splitpair(x.x, x.y, hi, lo);
  g_khi[g] = hi; g_klo[g] = lo;
}
__global__ void prep_q(const float* __restrict__ q){
  int g = blockIdx.x * blockDim.x + threadIdx.x;
  float2 x = *(const float2*)(q + (size_t)g*2);
  uint32_t hi, lo; splitpair(x.x, x.y, hi, lo);
  g_qhi[g] = hi; g_qlo[g] = lo;
}
__global__ void prep_v(const float* __restrict__ v, const float* __restrict__ rv){
  __shared__ uint16_t sh[128][66];
  int jt  = blockIdx.x;
  int h   = blockIdx.y;
  int blk = blockIdx.z;
  int tid = threadIdx.x;
  const float* src = (blk == 0) ? v : (rv + (size_t)(blk-1)*NP*NH*HD);
  #pragma unroll
  for (int i = 0; i < 8; i++){
    int f = i*256 + tid;
    int j = f >> 5; int d0 = (f & 31) << 2;
    float4 x = *(const float4*)(src + ((size_t)(jt*64 + j)*NH + h)*HD + d0);
    sh[d0+0][j] = f2h(x.x);
    sh[d0+1][j] = f2h(x.y);
    sh[d0+2][j] = f2h(x.z);
    sh[d0+3][j] = f2h(x.w);
  }
  __syncthreads();
  size_t base = ((size_t)(blk*NH + h)*128)*256 + jt*32;
  #pragma unroll
  for (int i = 0; i < 16; i++){
    int u = i*256 + tid;
    int d = u >> 5; int jp = u & 31;
    g_vtf[base + (size_t)d*256 + jp] = ((uint32_t)sh[d][jp*2+1] << 16) | sh[d][jp*2];
  }
}

// ================= main kernel =================
// smem (u32 units)
#define QH_OFF  0
#define QL_OFF  (QH_OFF + 128*68)
#define KH_OFF  (QL_OFF + 128*68)          // + buf*64*68
#define KL_OFF  (KH_OFF + 2*64*68)
#define VF_OFF  (KL_OFF + 2*64*68)         // + buf*128*36
#define P_OFF   (VF_OFF + 2*128*36)        // P fp16 [128 q][72 u16] = 128*36 u32
#define SL_OFF  (P_OFF + 128*36)           // l exchange: [wk 2][wq 8][16] floats
#define SMEM_U32 (SL_OFF + 256)            // 48896 u32 = 195584 B

static __device__ __forceinline__ void load_chunk(uint32_t sb, int t, int h, int buf, int tid){
  int blk = (t < 8) ? 0 : (1 + ((t - 8) >> 3));
  int j0  = ((t < 8) ? t : ((t - 8) & 7)) * BN;
  const uint32_t* kh = g_khi + ((size_t)(blk*NH + h)*512 + j0)*64;
  const uint32_t* kl = g_klo + ((size_t)(blk*NH + h)*512 + j0)*64;
  const uint32_t* vf = g_vtf + ((size_t)(blk*NH + h)*128)*256 + (j0 >> 1);
  uint32_t kdh = sb + (KH_OFF + buf*64*68)*4u;
  uint32_t kdl = sb + (KL_OFF + buf*64*68)*4u;
  uint32_t vdf = sb + (VF_OFF + buf*128*36)*4u;
  #pragma unroll
  for (int i = 0; i < 2; i++){
    int f = i*NT + tid;
    int row = f >> 4, seg = f & 15;        // K: 64 rows x 16 segs
    cpa16(kdh + (uint32_t)(row*68 + seg*4)*4u, kh + (size_t)row*64 + seg*4);
    cpa16(kdl + (uint32_t)(row*68 + seg*4)*4u, kl + (size_t)row*64 + seg*4);
    int vrow = f >> 3, vseg = f & 7;       // V: 128 rows x 8 segs
    cpa16(vdf + (uint32_t)(vrow*36 + vseg*4)*4u, vf + (size_t)vrow*256 + vseg*4);
  }
}

// One 64-key chunk, dim-split warp pair:
//  - QK: this warp's 32 keys (4 n-tiles), bf16 3-term
//  - P exchanged via smem (fp16)
//  - PV: this warp's 64 output dims (8 n-tiles), fp16 single-term
static __device__ __forceinline__ void do_chunk(
    uint32_t sb, int t, int h, int tid, int wk, int quad, int qt,
    uint32_t qa_h, uint32_t qa_l, uint32_t kb_off, uint32_t vb_off,
    uint32_t p_st_base, uint32_t p_ld_base,
    float (&o)[8][4], int a0, int a1, float& su0t, float& su1t)
{
  CP_WAIT0();
  __syncthreads();
  if (t + 1 < 24){
    load_chunk(sb, t+1, h, (t+1)&1, tid);
    CP_COMMIT();
  }

  const uint32_t kh_base = sb + (uint32_t)(KH_OFF + (t&1)*64*68)*4u + (uint32_t)(wk*32*68)*4u + kb_off;
  const uint32_t kl_base = kh_base + (uint32_t)(2*64*68)*4u;
  const uint32_t vf_base = sb + (uint32_t)(VF_OFF + (t&1)*128*36)*4u + (uint32_t)(wk*64*36)*4u + vb_off;

  // ---- QK^T (3-term bf16) over this warp's 32 keys
  float sf[4][4];
  #pragma unroll
  for (int n = 0; n < 4; n++)
    #pragma unroll
    for (int e = 0; e < 4; e++) sf[n][e] = 0.f;

  #pragma unroll
  for (int ks = 0; ks < 8; ks++){
    uint32_t ah[4], al[4];
    ldsm4(ah[0], ah[1], ah[2], ah[3], qa_h + ks*32u);
    ldsm4(al[0], al[1], al[2], al[3], qa_l + ks*32u);
    uint32_t B[2][4], C[2][4];
    #pragma unroll
    for (int np = 0; np < 2; np++){
      ldsm4(B[np][0], B[np][1], B[np][2], B[np][3], kh_base + (uint32_t)(np*16*68)*4u + ks*32u);
      ldsm4(C[np][0], C[np][1], C[np][2], C[np][3], kl_base + (uint32_t)(np*16*68)*4u + ks*32u);
    }
    #pragma unroll
    for (int np = 0; np < 2; np++){
      mma_bf16(sf[2*np],   ah, &B[np][0]);
      mma_bf16(sf[2*np+1], ah, &B[np][2]);
    }
    #pragma unroll
    for (int np = 0; np < 2; np++){
      mma_bf16(sf[2*np],   ah, &C[np][0]);
      mma_bf16(sf[2*np+1], ah, &C[np][2]);
    }
    #pragma unroll
    for (int np = 0; np < 2; np++){
      mma_bf16(sf[2*np],   al, &B[np][0]);
      mma_bf16(sf[2*np+1], al, &B[np][2]);
    }
  }

  // ---- exp, pack P fp16, store to smem exchange buffer
  float su0 = 0.f, su1 = 0.f;
  #pragma unroll
  for (int n = 0; n < 4; n++){
    float p0 = a0 ? __expf(sf[n][0]*SCALE) : 0.f;
    float p1 = a0 ? __expf(sf[n][1]*SCALE) : 0.f;
    float p2 = a1 ? __expf(sf[n][2]*SCALE) : 0.f;
    float p3 = a1 ? __expf(sf[n][3]*SCALE) : 0.f;
    su0 += p0 + p1; su1 += p2 + p3;
    uint32_t pa = packh(p0, p1);
    uint32_t pb = packh(p2, p3);
    // row quad -> col (wk*32 + n*8 + 2*qt); row quad+8 same col; pitch 72 u16 = 144B
    uint32_t addr = p_st_base + (uint32_t)(n*8)*2u;
    asm volatile("st.shared.b32 [%0], %1;" :: "r"(addr), "r"(pa) : "memory");
    asm volatile("st.shared.b32 [%0], %1;" :: "r"(addr + 8u*144u), "r"(pb) : "memory");
  }
  su0t += su0; su1t += su1;

  __syncthreads();   // P halves visible to the pair

  // ---- P@V (fp16): A-frags from smem P, this warp's 64 dims
  #pragma unroll
  for (int s = 0; s < 4; s++){
    uint32_t ph[4];
    ldsm4(ph[0], ph[1], ph[2], ph[3], p_ld_base + s*32u);
    uint32_t B[4][4];
    #pragma unroll
    for (int np = 0; np < 4; np++)
      ldsm4(B[np][0], B[np][1], B[np][2], B[np][3], vf_base + (uint32_t)(np*16*36)*4u + s*32u);
    #pragma unroll
    for (int np = 0; np < 4; np++){
      mma_f16(o[2*np],   ph, &B[np][0]);
      mma_f16(o[2*np+1], ph, &B[np][2]);
    }
  }
}

__global__ __launch_bounds__(NT, 1)
void regional_attn_main(const int* __restrict__ masks, float* __restrict__ out)
{
  extern __shared__ uint32_t smu[];
  const uint32_t sb = s2u(smu);
  float* sL = (float*)(smu + SL_OFF);
  const int tid  = threadIdx.x;
  const int lane = tid & 31;
  const int wid  = tid >> 5;
  const int wq   = wid >> 1;
  const int wk   = wid & 1;
  const int quad = lane >> 2;
  const int qt   = lane & 3;
  const int h = blockIdx.y;
  const int sBase = blockIdx.x * BM;

  {
    const uint32_t* qh = g_qhi + ((size_t)sBase*NH + h)*64;
    const uint32_t* ql = g_qlo + ((size_t)sBase*NH + h)*64;
    #pragma unroll
    for (int i = 0; i < 4; i++){
      int f = i*NT + tid;
      int row = f >> 4, seg = f & 15;
      cpa16(sb + (uint32_t)(QH_OFF + row*68 + seg*4)*4u, qh + (size_t)row*NH*64 + seg*4);
      cpa16(sb + (uint32_t)(QL_OFF + row*68 + seg*4)*4u, ql + (size_t)row*NH*64 + seg*4);
    }
  }
  load_chunk(sb, 0, h, 0, tid);
  CP_COMMIT();

  // ldmatrix lane addressing (A-frag pattern: m0=(r,h0) m1=(r+8,h0) m2=(r,h1) m3=(r+8,h1))
  const uint32_t lrow = lane & 7;
  const uint32_t lm   = (uint32_t)lane >> 3;
  const uint32_t qa_h = sb + (uint32_t)(QH_OFF + (wq*16 + (int)lrow + (int)((lm&1)*8))*68 + (int)((lm>>1)*4))*4u;
  const uint32_t qa_l = qa_h + (uint32_t)(128*68)*4u;
  // B-frag pattern: m0=(n,h0) m1=(n,h1) m2=(n+1,h0) m3=(n+1,h1)
  const uint32_t kb_off = (uint32_t)((((lm>>1)*8 + lrow)*68 + (lm&1)*4))*4u;
  const uint32_t vb_off = (uint32_t)((((lm>>1)*8 + lrow)*36 + (lm&1)*4))*4u;
  // P store (bytes): row (wq*16+quad), col (wk*32 + 2*qt), pitch 144B
  const uint32_t p_st_base = sb + (uint32_t)P_OFF*4u
      + (uint32_t)(wq*16 + quad)*144u + (uint32_t)(wk*32 + 2*qt)*2u;
  // P ldmatrix A-frag base (bytes)
  const uint32_t p_ld_base = sb + (uint32_t)P_OFF*4u
      + (uint32_t)(wq*16 + (int)lrow + (int)((lm&1)*8))*144u + (uint32_t)((lm>>1)*8)*2u;

  const int s0 = sBase + wq*16 + quad;
  const int s1 = s0 + 8;
  const int m0r0 = (masks[s0]      != 0), m0r1 = (masks[s1]      != 0);
  const int m1r0 = (masks[TS + s0] != 0), m1r1 = (masks[TS + s1] != 0);
  const int anyr0 = m0r0 | m1r0;
  const int anyr1 = m0r1 | m1r1;
  const unsigned FULL = 0xffffffffu;

  float o[8][4];
  #pragma unroll
  for (int n = 0; n < 8; n++)
    #pragma unroll
    for (int e = 0; e < 4; e++) o[n][e] = 0.f;

  float* o0p = out + (size_t)s0*(size_t)(NH*HD) + (size_t)h*HD + wk*64 + 2*qt;
  float* o1p = out + (size_t)s1*(size_t)(NH*HD) + (size_t)h*HD + wk*64 + 2*qt;

  // ---- base pass (chunks 0..7)
  {
    float l0 = 0.f, l1 = 0.f;
    #pragma unroll 1
    for (int t = 0; t < 8; t++)
      do_chunk(sb, t, h, tid, wk, quad, qt, qa_h, qa_l, kb_off, vb_off,
               p_st_base, p_ld_base, o, 1, 1, l0, l1);

    l0 += __shfl_xor_sync(FULL, l0, 1, 4); l0 += __shfl_xor_sync(FULL, l0, 2, 4);
    l1 += __shfl_xor_sync(FULL, l1, 1, 4); l1 += __shfl_xor_sync(FULL, l1, 2, 4);
    if (qt == 0){
      sL[(wk*8 + wq)*16 + quad]     = l0;
      sL[(wk*8 + wq)*16 + 8 + quad] = l1;
    }
    __syncthreads();
    float l0t = l0 + sL[((1-wk)*8 + wq)*16 + quad];
    float l1t = l1 + sL[((1-wk)*8 + wq)*16 + 8 + quad];

    const float w0 = (anyr0 ? 0.5f : 1.0f) / l0t;
    const float w1 = (anyr1 ? 0.5f : 1.0f) / l1t;
    #pragma unroll
    for (int n = 0; n < 8; n++){
      *(float2*)(o0p + n*8) = make_float2(o[n][0]*w0, o[n][1]*w0);
      *(float2*)(o1p + n*8) = make_float2(o[n][2]*w1, o[n][3]*w1);
      o[n][0] = 0.f; o[n][1] = 0.f; o[n][2] = 0.f; o[n][3] = 0.f;
    }
  }

  // ---- regional pass (chunks 8..23)
  {
    float l0 = 0.f, l1 = 0.f;
    #pragma unroll 1
    for (int t = 8; t < 16; t++)
      do_chunk(sb, t, h, tid, wk, quad, qt, qa_h, qa_l, kb_off, vb_off,
               p_st_base, p_ld_base, o, m0r0, m0r1, l0, l1);
    #pragma unroll 1
    for (int t = 16; t < 24; t++)
      do_chunk(sb, t, h, tid, wk, quad, qt, qa_h, qa_l, kb_off, vb_off,
               p_st_base, p_ld_base, o, m1r0, m1r1, l0, l1);

    l0 += __shfl_xor_sync(FULL, l0, 1, 4); l0 += __shfl_xor_sync(FULL, l0, 2, 4);
    l1 += __shfl_xor_sync(FULL, l1, 1, 4); l1 += __shfl_xor_sync(FULL, l1, 2, 4);
    __syncthreads();   // base-pass sL fully consumed
    if (qt == 0){
      sL[(wk*8 + wq)*16 + quad]     = l0;
      sL[(wk*8 + wq)*16 + 8 + quad] = l1;
    }
    __syncthreads();
    float l0t = l0 + sL[((1-wk)*8 + wq)*16 + quad];
    float l1t = l1 + sL[((1-wk)*8 + wq)*16 + 8 + quad];

    const float w0 = anyr0 ? (0.5f / l0t) : 0.f;
    const float w1 = anyr1 ? (0.5f / l1t) : 0.f;
    #pragma unroll
    for (int n = 0; n < 8; n++){
      float2 a = *(const float2*)(o0p + n*8);
      float2 b = *(const float2*)(o1p + n*8);
      a.x += o[n][0]*w0; a.y += o[n][1]*w0;
      b.x += o[n][2]*w1; b.y += o[n][3]*w1;
      *(float2*)(o0p + n*8) = a;
      *(float2*)(o1p + n*8) = b;
    }
  }
}

extern "C" void kernel_launch(void* const* d_in, const int* in_sizes, int n_in,
                              void* d_out, int out_size)
{
  const float* q     = (const float*)d_in[0];
  const float* k     = (const float*)d_in[1];
  const float* v     = (const float*)d_in[2];
  const float* rk    = (const float*)d_in[3];
  const float* rv    = (const float*)d_in[4];
  const int*   masks = (const int*)d_in[5];
  float* out = (float*)d_out;

  prep_k<<<3*16*512*64/256, 256>>>(k, rk);
  prep_q<<<4096*16*64/256, 256>>>(q);
  { dim3 g(8, 16, 3); prep_v<<<g, 256>>>(v, rv); }

  const int smem = SMEM_U32 * 4;
  cudaFuncSetAttribute(regional_attn_main,
                       cudaFuncAttributeMaxDynamicSharedMemorySize, smem);
  dim3 grid(TS / BM, NH);   // (32, 16)
  regional_attn_main<<<grid, NT, smem>>>(masks, out);
}

// round 14
// speedup vs baseline: 1.0349x; 1.0349x over previous
#include <cuda_runtime.h>
#include <cstdint>

#define TS 4096
#define NH 16
#define HD 128
#define NP 512
#define BM 128
#define BN 64
#define NT 256            // 8 warps: group A = wid 0..3, group B = wid 4..7
#define SCALE 0.08838834764831845f

// ---- device scratch ----
__device__ uint32_t g_khi[3*16*512*64];
__device__ uint32_t g_klo[3*16*512*64];
__device__ uint32_t g_vtf[3*16*128*256];   // fp16 V^T packed pairs
__device__ uint32_t g_qhi[4096*16*64];
__device__ uint32_t g_qlo[4096*16*64];

static __device__ __forceinline__ uint32_t s2u(const void* p){
  uint32_t a; asm("{ .reg .u64 t; cvta.to.shared.u64 t, %1; cvt.u32.u64 %0, t; }" : "=r"(a) : "l"(p)); return a;
}
static __device__ __forceinline__ uint16_t f2bf(float x){
  uint16_t r; asm("cvt.rn.bf16.f32 %0, %1;" : "=h"(r) : "f"(x)); return r;
}
static __device__ __forceinline__ float bf2f(uint16_t b){
  return __uint_as_float(((uint32_t)b) << 16);
}
static __device__ __forceinline__ uint16_t f2h(float x){
  uint16_t r; asm("cvt.rn.f16.f32 %0, %1;" : "=h"(r) : "f"(x)); return r;
}
static __device__ __forceinline__ uint32_t packbf(float x0, float x1){
  uint32_t r; asm("cvt.rn.bf16x2.f32 %0, %1, %2;" : "=r"(r) : "f"(x1), "f"(x0)); return r;
}
static __device__ __forceinline__ uint32_t packh(float x0, float x1){
  uint32_t r; asm("cvt.rn.f16x2.f32 %0, %1, %2;" : "=r"(r) : "f"(x1), "f"(x0)); return r;
}
static __device__ __forceinline__ void splitpair(float x0, float x1, uint32_t& hi, uint32_t& lo){
  hi = packbf(x0, x1);
  float h0 = bf2f((uint16_t)(hi & 0xffffu));
  float h1 = bf2f((uint16_t)(hi >> 16));
  lo = packbf(x0 - h0, x1 - h1);
}
static __device__ __forceinline__ void mma_bf16(float* d, const uint32_t* a, const uint32_t* b){
  asm volatile(
    "mma.sync.aligned.m16n8k16.row.col.f32.bf16.bf16.f32 "
    "{%0,%1,%2,%3}, {%4,%5,%6,%7}, {%8,%9}, {%0,%1,%2,%3};"
    : "+f"(d[0]), "+f"(d[1]), "+f"(d[2]), "+f"(d[3])
    : "r"(a[0]), "r"(a[1]), "r"(a[2]), "r"(a[3]), "r"(b[0]), "r"(b[1]));
}
static __device__ __forceinline__ void mma_f16(float* d, const uint32_t* a, const uint32_t* b){
  asm volatile(
    "mma.sync.aligned.m16n8k16.row.col.f32.f16.f16.f32 "
    "{%0,%1,%2,%3}, {%4,%5,%6,%7}, {%8,%9}, {%0,%1,%2,%3};"
    : "+f"(d[0]), "+f"(d[1]), "+f"(d[2]), "+f"(d[3])
    : "r"(a[0]), "r"(a[1]), "r"(a[2]), "r"(a[3]), "r"(b[0]), "r"(b[1]));
}
static __device__ __forceinline__ void ldsm4(uint32_t& r0, uint32_t& r1, uint32_t& r2, uint32_t& r3, uint32_t addr){
  asm volatile("ldmatrix.sync.aligned.m8n8.x4.shared.b16 {%0,%1,%2,%3}, [%4];"
               : "=r"(r0), "=r"(r1), "=r"(r2), "=r"(r3) : "r"(addr));
}
static __device__ __forceinline__ void cpa16(uint32_t dst, const void* src){
  asm volatile("cp.async.cg.shared.global [%0], [%1], 16;" :: "r"(dst), "l"(src) : "memory");
}
#define CP_COMMIT() asm volatile("cp.async.commit_group;" ::: "memory")
#define CP_WAIT0()  asm volatile("cp.async.wait_group 0;" ::: "memory")

// ================= pre-pass kernels (verified) =================
__global__ void prep_k(const float* __restrict__ k, const float* __restrict__ rk){
  int g = blockIdx.x * blockDim.x + threadIdx.x;
  int dp = g & 63; int r = g >> 6;
  int j = r & 511; r >>= 9;
  int h = r & 15;  int blk = r >> 4;
  const float* src = (blk == 0)
    ? (k  + ((size_t)j*NH + h)*HD + dp*2)
    : (rk + (((size_t)(blk-1)*NP + j)*NH + h)*HD + dp*2);
  float2 x = *(const float2*)src;
  uint32_t hi, lo; splitpair(x.x, x.y, hi, lo);
  g_khi[g] = hi; g_klo[g] = lo;
}
__global__ void prep_q(const float* __restrict__ q){
  int g = blockIdx.x * blockDim.x + threadIdx.x;
  float2 x = *(const float2*)(q + (size_t)g*2);
  uint32_t hi, lo; splitpair(x.x, x.y, hi, lo);
  g_qhi[g] = hi; g_qlo[g] = lo;
}
__global__ void prep_v(const float* __restrict__ v, const float* __restrict__ rv){
  __shared__ uint16_t sh[128][66];
  int jt  = blockIdx.x;
  int h   = blockIdx.y;
  int blk = blockIdx.z;
  int tid = threadIdx.x;
  const float* src = (blk == 0) ? v : (rv + (size_t)(blk-1)*NP*NH*HD);
  #pragma unroll
  for (int i = 0; i < 8; i++){
    int f = i*256 + tid;
    int j = f >> 5; int d0 = (f & 31) << 2;
    float4 x = *(const float4*)(src + ((size_t)(jt*64 + j)*NH + h)*HD + d0);
    sh[d0+0][j] = f2h(x.x);
    sh[d0+1][j] = f2h(x.y);
    sh[d0+2][j] = f2h(x.z);
    sh[d0+3][j] = f2h(x.w);
  }
  __syncthreads();
  size_t base = ((size_t)(blk*NH + h)*128)*256 + jt*32;
  #pragma unroll
  for (int i = 0; i < 16; i++){
    int u = i*256 + tid;
    int d = u >> 5; int jp = u & 31;
    g_vtf[base + (size_t)d*256 + jp] = ((uint32_t)sh[d][jp*2+1] << 16) | sh[d][jp*2];
  }
}

// ================= main kernel =================
#define QH_OFF  0
#define QL_OFF  (QH_OFF + 128*68)
#define KH_OFF  (QL_OFF + 128*68)          // + kbuf*64*68
#define KL_OFF  (KH_OFF + 2*64*68)
#define VF_OFF  (KL_OFF + 2*64*68)         // + vslot*128*36  (3-slot ring)
#define SMEM_U32 (VF_OFF + 3*128*36)       // 48640 u32 = 194560 B

static __device__ __forceinline__ void load_chunk(uint32_t sb, int t, int h, int kbuf, int vslot, int tid){
  int blk = (t < 8) ? 0 : (1 + ((t - 8) >> 3));
  int j0  = ((t < 8) ? t : ((t - 8) & 7)) * BN;
  const uint32_t* kh = g_khi + ((size_t)(blk*NH + h)*512 + j0)*64;
  const uint32_t* kl = g_klo + ((size_t)(blk*NH + h)*512 + j0)*64;
  const uint32_t* vf = g_vtf + ((size_t)(blk*NH + h)*128)*256 + (j0 >> 1);
  uint32_t kdh = sb + (KH_OFF + kbuf*64*68)*4u;
  uint32_t kdl = sb + (KL_OFF + kbuf*64*68)*4u;
  uint32_t vdf = sb + (VF_OFF + vslot*128*36)*4u;
  #pragma unroll
  for (int i = 0; i < 4; i++){
    int f = i*NT + tid;
    int row = f >> 4, seg = f & 15;        // K: 64 rows x 16 segs
    cpa16(kdh + (uint32_t)(row*68 + seg*4)*4u, kh + (size_t)row*64 + seg*4);
    cpa16(kdl + (uint32_t)(row*68 + seg*4)*4u, kl + (size_t)row*64 + seg*4);
    int vrow = f >> 3, vseg = f & 7;       // V: 128 rows x 8 segs
    cpa16(vdf + (uint32_t)(vrow*36 + vseg*4)*4u, vf + (size_t)vrow*256 + vseg*4);
  }
}

// PV: O += P(fp16) @ V(fp16), 4 k-steps x 16 n-tiles
static __device__ __forceinline__ void do_pv(uint32_t vf_base,
    const uint32_t (&pa)[8], const uint32_t (&pb)[8], float (&o)[16][4])
{
  #pragma unroll
  for (int s = 0; s < 4; s++){
    uint32_t ph[4] = { pa[2*s], pb[2*s], pa[2*s+1], pb[2*s+1] };
    #pragma unroll
    for (int g = 0; g < 2; g++){
      uint32_t B[4][4];
      #pragma unroll
      for (int i = 0; i < 4; i++){
        int np = g*4 + i;
        ldsm4(B[i][0], B[i][1], B[i][2], B[i][3], vf_base + (uint32_t)(np*2*8*36)*4u + s*32u);
      }
      #pragma unroll
      for (int i = 0; i < 4; i++){
        int np = g*4 + i;
        mma_f16(o[2*np],   ph, &B[i][0]);
        mma_f16(o[2*np+1], ph, &B[i][2]);
      }
    }
  }
}

// exp + fp16 pack of P, accumulating row sums
static __device__ __forceinline__ void do_exp(float (&sf)[8][4], int a0, int a1,
    uint32_t (&pa)[8], uint32_t (&pb)[8], float& su0t, float& su1t)
{
  float su0 = 0.f, su1 = 0.f;
  #pragma unroll
  for (int n = 0; n < 8; n++){
    float p0 = a0 ? __expf(sf[n][0]*SCALE) : 0.f;
    float p1 = a0 ? __expf(sf[n][1]*SCALE) : 0.f;
    float p2 = a1 ? __expf(sf[n][2]*SCALE) : 0.f;
    float p3 = a1 ? __expf(sf[n][3]*SCALE) : 0.f;
    su0 += p0 + p1; su1 += p2 + p3;
    pa[n] = packh(p0, p1);
    pb[n] = packh(p2, p3);
  }
  su0t += su0; su1t += su1;
}

// One chunk. Group A (deferB=0): QK -> exp -> PV(t).
// Group B (deferB=1): QK -> PV(t-1) (skipped at t==tstart) -> exp (P kept for next chunk).
static __device__ __forceinline__ void do_chunk(
    uint32_t sb, int t, int tstart, int h, int tid, int deferB,
    uint32_t qa_h, uint32_t qa_l, uint32_t kb_off, uint32_t vb_off,
    float (&o)[16][4], int a0, int a1, float& su0t, float& su1t,
    uint32_t (&pa)[8], uint32_t (&pb)[8])
{
  CP_WAIT0();
  __syncthreads();
  if (t + 1 < 24){
    load_chunk(sb, t+1, h, (t+1)&1, (t+1)%3, tid);
    CP_COMMIT();
  }

  const uint32_t kh_base = sb + (uint32_t)(KH_OFF + (t&1)*64*68)*4u + kb_off;
  const uint32_t kl_base = kh_base + (uint32_t)(2*64*68)*4u;
  const uint32_t vf_t    = sb + (uint32_t)(VF_OFF + (t%3)*128*36)*4u + vb_off;

  // ---- QK^T (3-term bf16): S = Qh*Kh + Qh*Kl + Ql*Kh
  float sf[8][4];
  #pragma unroll
  for (int n = 0; n < 8; n++)
    #pragma unroll
    for (int e = 0; e < 4; e++) sf[n][e] = 0.f;

  #pragma unroll
  for (int ks = 0; ks < 8; ks++){
    uint32_t ah[4], al[4];
    ldsm4(ah[0], ah[1], ah[2], ah[3], qa_h + ks*32u);
    ldsm4(al[0], al[1], al[2], al[3], qa_l + ks*32u);
    uint32_t B[4][4], C[4][4];
    #pragma unroll
    for (int np = 0; np < 4; np++){
      ldsm4(B[np][0], B[np][1], B[np][2], B[np][3], kh_base + (uint32_t)(np*2*8*68)*4u + ks*32u);
      ldsm4(C[np][0], C[np][1], C[np][2], C[np][3], kl_base + (uint32_t)(np*2*8*68)*4u + ks*32u);
    }
    #pragma unroll
    for (int np = 0; np < 4; np++){
      mma_bf16(sf[2*np],   ah, &B[np][0]);
      mma_bf16(sf[2*np+1], ah, &B[np][2]);
    }
    #pragma unroll
    for (int np = 0; np < 4; np++){
      mma_bf16(sf[2*np],   ah, &C[np][0]);
      mma_bf16(sf[2*np+1], ah, &C[np][2]);
    }
    #pragma unroll
    for (int np = 0; np < 4; np++){
      mma_bf16(sf[2*np],   al, &B[np][0]);
      mma_bf16(sf[2*np+1], al, &B[np][2]);
    }
  }

  if (!deferB){
    do_exp(sf, a0, a1, pa, pb, su0t, su1t);
    do_pv(vf_t, pa, pb, o);
  } else {
    if (t > tstart){
      int tp = t - 1;
      uint32_t vf_p = sb + (uint32_t)(VF_OFF + (tp%3)*128*36)*4u + vb_off;
      do_pv(vf_p, pa, pb, o);
    }
    do_exp(sf, a0, a1, pa, pb, su0t, su1t);
  }
}

__global__ __launch_bounds__(NT, 1)
void regional_attn_main(const int* __restrict__ masks, float* __restrict__ out)
{
  extern __shared__ uint32_t smu[];
  const uint32_t sb = s2u(smu);
  const int tid  = threadIdx.x;
  const int lane = tid & 31;
  const int wid  = tid >> 5;
  const int quad = lane >> 2;
  const int qt   = lane & 3;
  const int deferB = (wid >> 2) & 1;       // one A and one B warp per SMSP
  const int h = blockIdx.y;
  const int sBase = blockIdx.x * BM;

  {
    const uint32_t* qh = g_qhi + ((size_t)sBase*NH + h)*64;
    const uint32_t* ql = g_qlo + ((size_t)sBase*NH + h)*64;
    #pragma unroll
    for (int i = 0; i < 8; i++){
      int f = i*NT + tid;
      int row = f >> 4, seg = f & 15;
      cpa16(sb + (uint32_t)(QH_OFF + row*68 + seg*4)*4u, qh + (size_t)row*NH*64 + seg*4);
      cpa16(sb + (uint32_t)(QL_OFF + row*68 + seg*4)*4u, ql + (size_t)row*NH*64 + seg*4);
    }
  }
  load_chunk(sb, 0, h, 0, 0, tid);
  CP_COMMIT();

  const uint32_t lrow = lane & 7;
  const uint32_t lm   = (uint32_t)lane >> 3;
  const uint32_t qa_h = sb + (uint32_t)(QH_OFF + (wid*16 + (int)lrow + (int)((lm&1)*8))*68 + (int)((lm>>1)*4))*4u;
  const uint32_t qa_l = qa_h + (uint32_t)(128*68)*4u;
  const uint32_t kb_off = (uint32_t)((((lm>>1)*8 + lrow)*68 + (lm&1)*4))*4u;
  const uint32_t vb_off = (uint32_t)((((lm>>1)*8 + lrow)*36 + (lm&1)*4))*4u;

  const int s0 = sBase + wid*16 + quad;
  const int s1 = s0 + 8;
  const int m0r0 = (masks[s0]      != 0), m0r1 = (masks[s1]      != 0);
  const int m1r0 = (masks[TS + s0] != 0), m1r1 = (masks[TS + s1] != 0);
  const int anyr0 = m0r0 | m1r0;
  const int anyr1 = m0r1 | m1r1;
  const unsigned FULL = 0xffffffffu;

  float o[16][4];
  #pragma unroll
  for (int n = 0; n < 16; n++)
    #pragma unroll
    for (int e = 0; e < 4; e++) o[n][e] = 0.f;

  uint32_t pa[8], pb[8];                   // P fragments (persistent for group B)

  float* o0p = out + (size_t)s0*(size_t)(NH*HD) + (size_t)h*HD + 2*qt;
  float* o1p = out + (size_t)s1*(size_t)(NH*HD) + (size_t)h*HD + 2*qt;

  // ---- base pass (chunks 0..7)
  {
    float l0 = 0.f, l1 = 0.f;
    #pragma unroll 1
    for (int t = 0; t < 8; t++)
      do_chunk(sb, t, 0, h, tid, deferB, qa_h, qa_l, kb_off, vb_off,
               o, 1, 1, l0, l1, pa, pb);
    if (deferB){   // flush PV(7): V slot 7%3 = 1
      do_pv(sb + (uint32_t)(VF_OFF + 1*128*36)*4u + vb_off, pa, pb, o);
    }

    l0 += __shfl_xor_sync(FULL, l0, 1, 4); l0 += __shfl_xor_sync(FULL, l0, 2, 4);
    l1 += __shfl_xor_sync(FULL, l1, 1, 4); l1 += __shfl_xor_sync(FULL, l1, 2, 4);
    const float w0 = (anyr0 ? 0.5f : 1.0f) / l0;
    const float w1 = (anyr1 ? 0.5f : 1.0f) / l1;
    #pragma unroll
    for (int n = 0; n < 16; n++){
      *(float2*)(o0p + n*8) = make_float2(o[n][0]*w0, o[n][1]*w0);
      *(float2*)(o1p + n*8) = make_float2(o[n][2]*w1, o[n][3]*w1);
      o[n][0] = 0.f; o[n][1] = 0.f; o[n][2] = 0.f; o[n][3] = 0.f;
    }
  }

  // ---- regional pass (chunks 8..23)
  {
    float l0 = 0.f, l1 = 0.f;
    #pragma unroll 1
    for (int t = 8; t < 16; t++)
      do_chunk(sb, t, 8, h, tid, deferB, qa_h, qa_l, kb_off, vb_off,
               o, m0r0, m0r1, l0, l1, pa, pb);
    #pragma unroll 1
    for (int t = 16; t < 24; t++)
      do_chunk(sb, t, 8, h, tid, deferB, qa_h, qa_l, kb_off, vb_off,
               o, m1r0, m1r1, l0, l1, pa, pb);
    if (deferB){   // flush PV(23): V slot 23%3 = 2
      do_pv(sb + (uint32_t)(VF_OFF + 2*128*36)*4u + vb_off, pa, pb, o);
    }

    l0 += __shfl_xor_sync(FULL, l0, 1, 4); l0 += __shfl_xor_sync(FULL, l0, 2, 4);
    l1 += __shfl_xor_sync(FULL, l1, 1, 4); l1 += __shfl_xor_sync(FULL, l1, 2, 4);
    const float w0 = anyr0 ? (0.5f / l0) : 0.f;
    const float w1 = anyr1 ? (0.5f / l1) : 0.f;
    #pragma unroll
    for (int n = 0; n < 16; n++){
      float2 a = *(const float2*)(o0p + n*8);
      float2 b = *(const float2*)(o1p + n*8);
      a.x += o[n][0]*w0; a.y += o[n][1]*w0;
      b.x += o[n][2]*w1; b.y += o[n][3]*w1;
      *(float2*)(o0p + n*8) = a;
      *(float2*)(o1p + n*8) = b;
    }
  }
}

extern "C" void kernel_launch(void* const* d_in, const int* in_sizes, int n_in,
                              void* d_out, int out_size)
{
  const float* q     = (const float*)d_in[0];
  const float* k     = (const float*)d_in[1];
  const float* v     = (const float*)d_in[2];
  const float* rk    = (const float*)d_in[3];
  const float* rv    = (const float*)d_in[4];
  const int*   masks = (const int*)d_in[5];
  float* out = (float*)d_out;

  prep_k<<<3*16*512*64/256, 256>>>(k, rk);
  prep_q<<<4096*16*64/256, 256>>>(q);
  { dim3 g(8, 16, 3); prep_v<<<g, 256>>>(v, rv); }

  const int smem = SMEM_U32 * 4;
  cudaFuncSetAttribute(regional_attn_main,
                       cudaFuncAttributeMaxDynamicSharedMemorySize, smem);
  dim3 grid(TS / BM, NH);   // (32, 16)
  regional_attn_main<<<grid, NT, smem>>>(masks, out);
}